// round 9
// baseline (speedup 1.0000x reference)
#include <cuda_runtime.h>
#include <cstdint>

#define NN 100000
#define EE 1000000
#define HID 64
#define BN_EPS 1e-5f

// ---------------- scratch: __device__ globals, referenced ONLY in device code ----------------
__device__ int    g_is64;                  // 1 if edge_index is int64, 0 if int32
__device__ float  g_dinv[NN];              // degree -> rsqrt(degree)
__device__ float  g_h[(size_t)NN * HID];   // per-layer transformed features
__device__ float  g_agg[(size_t)NN * HID]; // aggregation accumulator
__device__ float  g_xA[(size_t)NN * HID];  // layer-1 output
__device__ float  g_xB[(size_t)NN * HID];  // layer-2 output
__device__ float4 g_edge[EE];              // packed edge: (row-bits, col-bits, en, 0)

// ---------------- dtype detection: int64 vs int32 edge_index ----------------
// Under int64: every high 32-bit word is 0 (indices < 100000 << 2^31).
// Under int32: the .y slots hold real indices, nonzero w.h.p.
// Scan head AND tail regions of the safely-readable int32 extent (E pairs of
// int32 = E 8-byte slots; always within the buffer for either dtype).
__global__ void k_detect(const void* ei, int nPairs) {
    __shared__ int sawHi;
    if (threadIdx.x == 0) sawHi = 0;
    __syncthreads();
    const int2* p = (const int2*)ei;
    int scan = nPairs < 2048 ? nPairs : 2048;
    for (int i = threadIdx.x; i < scan; i += blockDim.x) {
        if (p[i].y != 0) sawHi = 1;
        if (p[nPairs - 1 - i].y != 0) sawHi = 1;
    }
    __syncthreads();
    if (threadIdx.x == 0) g_is64 = sawHi ? 0 : 1;
}

__device__ __forceinline__ int edge_at(const void* ei, size_t idx) {
    return g_is64 ? (int)((const long long*)ei)[idx] : ((const int*)ei)[idx];
}

// ---------------- degree / norm precompute ----------------
__global__ void k_deg_init(int N) {
    int i = blockIdx.x * blockDim.x + threadIdx.x;
    if (i < N) g_dinv[i] = 1.0f;  // self loop
}

__global__ void k_deg_count(const void* ei, int E, int N) {
    int e = blockIdx.x * blockDim.x + threadIdx.x;
    if (e < E) {
        int c = edge_at(ei, (size_t)E + e);
        if ((unsigned)c < (unsigned)N) atomicAdd(&g_dinv[c], 1.0f);
    }
}

__global__ void k_dinv(int N) {
    int i = blockIdx.x * blockDim.x + threadIdx.x;
    if (i < N) g_dinv[i] = rsqrtf(g_dinv[i]);   // deg >= 1 always (self loops)
}

// builds the packed edge records; indices clamped in-bounds here once.
__global__ void k_enorm(const void* ei, int E, int N) {
    int e = blockIdx.x * blockDim.x + threadIdx.x;
    if (e < E) {
        int r = edge_at(ei, e);
        int c = edge_at(ei, (size_t)E + e);
        if ((unsigned)r >= (unsigned)N) r = 0;
        if ((unsigned)c >= (unsigned)N) c = 0;
        float4 rec;
        rec.x = __int_as_float(r);
        rec.y = __int_as_float(c);
        rec.z = g_dinv[r] * g_dinv[c];
        rec.w = 0.0f;
        g_edge[e] = rec;
    }
}

// ---------------- GEMM: h = src @ W ; agg = dinv^2 * h (self-loop init) ----------------
// src selected on-device by mode: 0 -> external x, 1 -> g_xA, 2 -> g_xB.
template <int K>
__global__ void k_gemm_selfinit(const float* __restrict__ x, const float* __restrict__ W,
                                int mode, int N) {
    const float* src = (mode == 0) ? x : (mode == 1 ? g_xA : g_xB);
    int n = threadIdx.x & 63;
    int slot = threadIdx.x >> 6;  // 0..3
    float w[K];
#pragma unroll
    for (int k = 0; k < K; k++) w[k] = W[k * HID + n];

    int rowBase = blockIdx.x * 64;
#pragma unroll 4
    for (int it = 0; it < 16; it++) {
        int m = rowBase + it * 4 + slot;
        if (m < N) {
            const float* xr = src + (size_t)m * K;
            float acc = 0.0f;
#pragma unroll
            for (int k = 0; k < K; k++) acc = fmaf(xr[k], w[k], acc);
            size_t o = (size_t)m * HID + n;
            g_h[o] = acc;
            float d = g_dinv[m];
            g_agg[o] = d * d * acc;
        }
    }
}

// ---------------- scatter: agg[col] += enorm * h[row] ----------------
// 16 threads per edge; one LDG.128 edge record (broadcast across the 16 lanes),
// float4 feature gather, 4 scalar atomicAdd (compile to RED.E.ADD.F32).
__global__ void k_scatter(int E) {
    int gid = blockIdx.x * blockDim.x + threadIdx.x;
    int e = gid >> 4;
    if (e >= E) return;
    int lane = gid & 15;
    float4 rec = g_edge[e];
    int r = __float_as_int(rec.x);
    int c = __float_as_int(rec.y);
    float s = rec.z;
    float4 hv = *(reinterpret_cast<const float4*>(g_h + (size_t)r * HID) + lane);
    float* dst = g_agg + (size_t)c * HID + lane * 4;
    atomicAdd(dst + 0, hv.x * s);
    atomicAdd(dst + 1, hv.y * s);
    atomicAdd(dst + 2, hv.z * s);
    atomicAdd(dst + 3, hv.w * s);
}

// ---------------- epilogue: bias + BN(eval) + relu + residual (float4-vectorized) ----------------
// mode: 0 = write g_xA (no residual), 1 = +g_xA -> g_xB, 2 = +g_xB -> out
__global__ void k_epilogue(const float* __restrict__ b, const float* __restrict__ gamma,
                           const float* __restrict__ beta, const float* __restrict__ mean,
                           const float* __restrict__ var, float* __restrict__ out,
                           int mode, int totalVec) {
    int v4 = blockIdx.x * blockDim.x + threadIdx.x;
    if (v4 >= totalVec) return;
    int nb = (v4 * 4) & 63;   // starting column of this float4 (HID divisible by 4)
    float4 a = reinterpret_cast<const float4*>(g_agg)[v4];
    float r0, r1, r2, r3;
    {
        float v;
        v = a.x + b[nb + 0]; v = (v - mean[nb + 0]) * rsqrtf(var[nb + 0] + BN_EPS) * gamma[nb + 0] + beta[nb + 0]; r0 = fmaxf(v, 0.0f);
        v = a.y + b[nb + 1]; v = (v - mean[nb + 1]) * rsqrtf(var[nb + 1] + BN_EPS) * gamma[nb + 1] + beta[nb + 1]; r1 = fmaxf(v, 0.0f);
        v = a.z + b[nb + 2]; v = (v - mean[nb + 2]) * rsqrtf(var[nb + 2] + BN_EPS) * gamma[nb + 2] + beta[nb + 2]; r2 = fmaxf(v, 0.0f);
        v = a.w + b[nb + 3]; v = (v - mean[nb + 3]) * rsqrtf(var[nb + 3] + BN_EPS) * gamma[nb + 3] + beta[nb + 3]; r3 = fmaxf(v, 0.0f);
    }
    float4 res;
    if (mode == 0) {
        res.x = r0; res.y = r1; res.z = r2; res.w = r3;
        reinterpret_cast<float4*>(g_xA)[v4] = res;
    } else if (mode == 1) {
        float4 pr = reinterpret_cast<const float4*>(g_xA)[v4];
        res.x = r0 + pr.x; res.y = r1 + pr.y; res.z = r2 + pr.z; res.w = r3 + pr.w;
        reinterpret_cast<float4*>(g_xB)[v4] = res;
    } else {
        float4 pr = reinterpret_cast<const float4*>(g_xB)[v4];
        res.x = r0 + pr.x; res.y = r1 + pr.y; res.z = r2 + pr.z; res.w = r3 + pr.w;
        reinterpret_cast<float4*>(out)[v4] = res;
    }
}

// ---------------- launch ----------------
extern "C" void kernel_launch(void* const* d_in, const int* in_sizes, int n_in,
                              void* d_out, int out_size) {
    const float* x   = (const float*)d_in[0];
    const void*  ei  = d_in[1];               // int32 or int64, detected on device
    const float* W1  = (const float*)d_in[2];
    const float* W2  = (const float*)d_in[3];
    const float* W3  = (const float*)d_in[4];
    const float* b   = (const float*)d_in[5];
    const float* gm  = (const float*)d_in[6];
    const float* bt  = (const float*)d_in[7];
    const float* rm  = (const float*)d_in[8];
    const float* rv  = (const float*)d_in[9];
    float* out = (float*)d_out;

    const int N = in_sizes[0] / 37;   // 100000
    const int E = in_sizes[1] / 2;    // 1000000

    const int T = 256;
    // dtype detection + degree + edge norms (once; reused by all 3 layers)
    k_detect<<<1, 256>>>(ei, E);  // E pairs of int32 = E 8-byte slots, safe bound
    k_deg_init<<<(N + T - 1) / T, T>>>(N);
    k_deg_count<<<(E + T - 1) / T, T>>>(ei, E, N);
    k_dinv<<<(N + T - 1) / T, T>>>(N);
    k_enorm<<<(E + T - 1) / T, T>>>(ei, E, N);

    const int gemmGrid = (N + 63) / 64;
    const long long scatThreads = (long long)E * 16;
    const int scatGrid = (int)((scatThreads + T - 1) / T);
    const int totalVec = N * HID / 4;
    const int epiGrid = (totalVec + T - 1) / T;

    // layer 0: x(37) -> g_xA  (no residual: dims differ)
    k_gemm_selfinit<37><<<gemmGrid, T>>>(x, W1, 0, N);
    k_scatter<<<scatGrid, T>>>(E);
    k_epilogue<<<epiGrid, T>>>(b + 0 * HID, gm + 0 * HID, bt + 0 * HID,
                               rm + 0 * HID, rv + 0 * HID, out, 0, totalVec);

    // layer 1: g_xA -> g_xB (residual g_xA)
    k_gemm_selfinit<64><<<gemmGrid, T>>>(x, W2, 1, N);
    k_scatter<<<scatGrid, T>>>(E);
    k_epilogue<<<epiGrid, T>>>(b + 1 * HID, gm + 1 * HID, bt + 1 * HID,
                               rm + 1 * HID, rv + 1 * HID, out, 1, totalVec);

    // layer 2: g_xB -> out (residual g_xB)
    k_gemm_selfinit<64><<<gemmGrid, T>>>(x, W3, 2, N);
    k_scatter<<<scatGrid, T>>>(E);
    k_epilogue<<<epiGrid, T>>>(b + 2 * HID, gm + 2 * HID, bt + 2 * HID,
                               rm + 2 * HID, rv + 2 * HID, out, 2, totalVec);
}

// round 12
// speedup vs baseline: 1.8559x; 1.8559x over previous
#include <cuda_runtime.h>
#include <cstdint>

#define NN 100000
#define EE 1000000
#define HID 64
#define BN_EPS 1e-5f
#define T 256

// ---------------- scratch: __device__ globals, referenced ONLY in device code ----------------
__device__ int   g_is64;                   // 1 if edge_index is int64, 0 if int32
__device__ int   g_cnt[NN];                // in-degree counts (excl self loop)
__device__ int   g_rowptr[NN + 1];         // CSR row pointers (by target node)
__device__ int   g_cur[NN];                // fill cursors
__device__ int   g_bsum[(NN + T - 1) / T + 1]; // block partial sums for scan
__device__ float g_dinv[NN];               // rsqrt(1 + deg)
__device__ int2  g_csr[EE];                // packed edge: (src, enorm-bits)
__device__ float g_h[(size_t)NN * HID];    // per-layer transformed features
__device__ float g_xA[(size_t)NN * HID];   // layer-1 output
__device__ float g_xB[(size_t)NN * HID];   // layer-2 output

// ---------------- dtype detection: int64 vs int32 edge_index ----------------
__global__ void k_detect(const void* ei, int nPairs) {
    __shared__ int sawHi;
    if (threadIdx.x == 0) sawHi = 0;
    __syncthreads();
    const int2* p = (const int2*)ei;
    int scan = nPairs < 2048 ? nPairs : 2048;
    for (int i = threadIdx.x; i < scan; i += blockDim.x) {
        if (p[i].y != 0) sawHi = 1;
        if (p[nPairs - 1 - i].y != 0) sawHi = 1;
    }
    __syncthreads();
    if (threadIdx.x == 0) g_is64 = sawHi ? 0 : 1;
}

__device__ __forceinline__ int edge_at(const void* ei, size_t idx) {
    return g_is64 ? (int)((const long long*)ei)[idx] : ((const int*)ei)[idx];
}

// ---------------- CSR build ----------------
__global__ void k_zero(int N) {
    int i = blockIdx.x * blockDim.x + threadIdx.x;
    if (i < N) g_cnt[i] = 0;
}

__global__ void k_count(const void* ei, int E, int N) {
    int e = blockIdx.x * blockDim.x + threadIdx.x;
    if (e < E) {
        int c = edge_at(ei, (size_t)E + e);
        if ((unsigned)c < (unsigned)N) atomicAdd(&g_cnt[c], 1);
    }
}

// block-level exclusive scan of g_cnt -> g_rowptr (in-block exclusive), block totals -> g_bsum
__global__ void k_scan_block(int N) {
    __shared__ int s[T];
    int i = blockIdx.x * T + threadIdx.x;
    int v = (i < N) ? g_cnt[i] : 0;
    s[threadIdx.x] = v;
    __syncthreads();
    // Hillis-Steele inclusive scan
    for (int off = 1; off < T; off <<= 1) {
        int add = (threadIdx.x >= off) ? s[threadIdx.x - off] : 0;
        __syncthreads();
        s[threadIdx.x] += add;
        __syncthreads();
    }
    if (i < N) g_rowptr[i] = s[threadIdx.x] - v;  // exclusive within block
    if (threadIdx.x == T - 1) g_bsum[blockIdx.x] = s[T - 1];
}

// single-block exclusive scan of block sums (nb <= 512)
__global__ void k_scan_top(int nb) {
    __shared__ int s[512];
    int v = (threadIdx.x < nb) ? g_bsum[threadIdx.x] : 0;
    s[threadIdx.x] = v;
    __syncthreads();
    for (int off = 1; off < 512; off <<= 1) {
        int add = (threadIdx.x >= off) ? s[threadIdx.x - off] : 0;
        __syncthreads();
        s[threadIdx.x] += add;
        __syncthreads();
    }
    if (threadIdx.x < nb) g_bsum[threadIdx.x] = s[threadIdx.x] - v;  // exclusive
}

// add block offsets; compute dinv; zero cursors; write rowptr[N]=E
__global__ void k_scan_add(int N, int E) {
    int i = blockIdx.x * blockDim.x + threadIdx.x;
    if (i < N) {
        g_rowptr[i] += g_bsum[blockIdx.x];
        g_dinv[i] = rsqrtf(1.0f + (float)g_cnt[i]);
        g_cur[i] = 0;
    }
    if (i == 0) g_rowptr[N] = E;
}

__global__ void k_fill(const void* ei, int E, int N) {
    int e = blockIdx.x * blockDim.x + threadIdx.x;
    if (e < E) {
        int r = edge_at(ei, e);
        int c = edge_at(ei, (size_t)E + e);
        if ((unsigned)r >= (unsigned)N) r = 0;
        if ((unsigned)c >= (unsigned)N) c = 0;
        int pos = g_rowptr[c] + atomicAdd(&g_cur[c], 1);
        int2 rec;
        rec.x = r;
        rec.y = __float_as_int(g_dinv[r] * g_dinv[c]);
        g_csr[pos] = rec;
    }
}

// ---------------- GEMM: h = src @ W (src selected on-device by mode) ----------------
template <int K>
__global__ void k_gemm(const float* __restrict__ x, const float* __restrict__ W,
                       int mode, int N) {
    const float* src = (mode == 0) ? x : (mode == 1 ? g_xA : g_xB);
    int n = threadIdx.x & 63;
    int slot = threadIdx.x >> 6;  // 0..3
    float w[K];
#pragma unroll
    for (int k = 0; k < K; k++) w[k] = W[k * HID + n];

    int rowBase = blockIdx.x * 64;
#pragma unroll 4
    for (int it = 0; it < 16; it++) {
        int m = rowBase + it * 4 + slot;
        if (m < N) {
            const float* xr = src + (size_t)m * K;
            float acc = 0.0f;
#pragma unroll
            for (int k = 0; k < K; k++) acc = fmaf(xr[k], w[k], acc);
            g_h[(size_t)m * HID + n] = acc;
        }
    }
}

// ---------------- fused aggregation + epilogue ----------------
// 16 lanes per node; register accumulation over incoming edges (atomic-free),
// self-loop init, then bias + BN(eval) + relu + residual, direct output write.
// Edge record stream software-pipelined (1-deep prefetch) to break the
// rec->addr->hv dependency chain at L2 latency.
// mode: 0 -> g_xA (no residual), 1 -> +g_xA -> g_xB, 2 -> +g_xB -> out
__global__ void k_aggfuse(const float* __restrict__ b, const float* __restrict__ gamma,
                          const float* __restrict__ beta, const float* __restrict__ mean,
                          const float* __restrict__ var, float* __restrict__ out,
                          int mode, int N) {
    int gid = blockIdx.x * blockDim.x + threadIdx.x;
    int c = gid >> 4;
    if (c >= N) return;
    int lane = gid & 15;

    const float4* hrow = reinterpret_cast<const float4*>(g_h);
    float d = g_dinv[c];
    float4 acc = hrow[(size_t)c * 16 + lane];
    float dd = d * d;
    acc.x *= dd; acc.y *= dd; acc.z *= dd; acc.w *= dd;

    int beg = g_rowptr[c];
    int end = g_rowptr[c + 1];
    if (beg < end) {
        int2 rec = g_csr[beg];               // broadcast across the 16 lanes
        for (int j = beg; j < end; j++) {
            int jn = j + 1 < end ? j + 1 : j;
            int2 recN = g_csr[jn];           // prefetch next record (in-bounds clamp)
            float s = __int_as_float(rec.y);
            float4 hv = hrow[(size_t)rec.x * 16 + lane];
            acc.x = fmaf(hv.x, s, acc.x);
            acc.y = fmaf(hv.y, s, acc.y);
            acc.z = fmaf(hv.z, s, acc.z);
            acc.w = fmaf(hv.w, s, acc.w);
            rec = recN;
        }
    }

    int nb = lane * 4;
    float r0, r1, r2, r3;
    {
        float v;
        v = acc.x + b[nb + 0]; v = (v - mean[nb + 0]) * rsqrtf(var[nb + 0] + BN_EPS) * gamma[nb + 0] + beta[nb + 0]; r0 = fmaxf(v, 0.0f);
        v = acc.y + b[nb + 1]; v = (v - mean[nb + 1]) * rsqrtf(var[nb + 1] + BN_EPS) * gamma[nb + 1] + beta[nb + 1]; r1 = fmaxf(v, 0.0f);
        v = acc.z + b[nb + 2]; v = (v - mean[nb + 2]) * rsqrtf(var[nb + 2] + BN_EPS) * gamma[nb + 2] + beta[nb + 2]; r2 = fmaxf(v, 0.0f);
        v = acc.w + b[nb + 3]; v = (v - mean[nb + 3]) * rsqrtf(var[nb + 3] + BN_EPS) * gamma[nb + 3] + beta[nb + 3]; r3 = fmaxf(v, 0.0f);
    }

    size_t vidx = (size_t)c * 16 + lane;
    float4 res;
    if (mode == 0) {
        res.x = r0; res.y = r1; res.z = r2; res.w = r3;
        reinterpret_cast<float4*>(g_xA)[vidx] = res;
    } else if (mode == 1) {
        float4 pr = reinterpret_cast<const float4*>(g_xA)[vidx];
        res.x = r0 + pr.x; res.y = r1 + pr.y; res.z = r2 + pr.z; res.w = r3 + pr.w;
        reinterpret_cast<float4*>(g_xB)[vidx] = res;
    } else {
        float4 pr = reinterpret_cast<const float4*>(g_xB)[vidx];
        res.x = r0 + pr.x; res.y = r1 + pr.y; res.z = r2 + pr.z; res.w = r3 + pr.w;
        reinterpret_cast<float4*>(out)[vidx] = res;
    }
}

// ---------------- launch ----------------
extern "C" void kernel_launch(void* const* d_in, const int* in_sizes, int n_in,
                              void* d_out, int out_size) {
    const float* x   = (const float*)d_in[0];
    const void*  ei  = d_in[1];               // int32 or int64, detected on device
    const float* W1  = (const float*)d_in[2];
    const float* W2  = (const float*)d_in[3];
    const float* W3  = (const float*)d_in[4];
    const float* b   = (const float*)d_in[5];
    const float* gm  = (const float*)d_in[6];
    const float* bt  = (const float*)d_in[7];
    const float* rm  = (const float*)d_in[8];
    const float* rv  = (const float*)d_in[9];
    float* out = (float*)d_out;

    const int N = in_sizes[0] / 37;   // 100000
    const int E = in_sizes[1] / 2;    // 1000000

    const int nBlk = (N + T - 1) / T;
    const int eBlk = (E + T - 1) / T;

    // ---- one-time CSR build (reused by all 3 layers) ----
    k_detect<<<1, 256>>>(ei, E);
    k_zero<<<nBlk, T>>>(N);
    k_count<<<eBlk, T>>>(ei, E, N);
    k_scan_block<<<nBlk, T>>>(N);
    k_scan_top<<<1, 512>>>(nBlk);
    k_scan_add<<<nBlk, T>>>(N, E);
    k_fill<<<eBlk, T>>>(ei, E, N);

    const int gemmGrid = (N + 63) / 64;
    const int aggGrid = (N * 16 + T - 1) / T;

    // layer 0: x(37) -> g_xA  (no residual: dims differ)
    k_gemm<37><<<gemmGrid, T>>>(x, W1, 0, N);
    k_aggfuse<<<aggGrid, T>>>(b + 0 * HID, gm + 0 * HID, bt + 0 * HID,
                              rm + 0 * HID, rv + 0 * HID, out, 0, N);

    // layer 1: g_xA -> g_xB (residual g_xA)
    k_gemm<64><<<gemmGrid, T>>>(x, W2, 1, N);
    k_aggfuse<<<aggGrid, T>>>(b + 1 * HID, gm + 1 * HID, bt + 1 * HID,
                              rm + 1 * HID, rv + 1 * HID, out, 1, N);

    // layer 2: g_xB -> out (residual g_xB)
    k_gemm<64><<<gemmGrid, T>>>(x, W3, 2, N);
    k_aggfuse<<<aggGrid, T>>>(b + 2 * HID, gm + 2 * HID, bt + 2 * HID,
                              rm + 2 * HID, rv + 2 * HID, out, 2, N);
}